// round 2
// baseline (speedup 1.0000x reference)
#include <cuda_runtime.h>
#include <math.h>
#include <stdint.h>

#define BB 8
#define NN 8192
#define NP 2048
#define NS 32
#define DINC 61
#define DD 64

// ---------------- scratch (static device globals; no allocation) ----------------
__device__ float g_newxyz[BB * NP * 3];
__device__ int   g_gi[BB * NP * NS];
__device__ float g_feat2[BB * NP * DD];
__device__ float g_q[BB * NP * DD];
__device__ float g_k[BB * NP * DD];
__device__ float g_v[BB * NP * DD];
__device__ float g_o[BB * NP * DD];

// ---------------- FPS: one block per batch, xyz+dists in smem ----------------
__global__ void __launch_bounds__(1024) fps_kernel(const float* __restrict__ xyz,
                                                   float* __restrict__ out1) {
    extern __shared__ float sm[];
    float* sx   = sm;
    float* sy   = sm + NN;
    float* sz   = sm + 2 * NN;
    float* dist = sm + 3 * NN;
    float* wval = sm + 4 * NN;            // 32
    int*   widx = (int*)(wval + 32);      // 32
    int*   scur = widx + 32;              // 1

    const int b   = blockIdx.x;
    const int tid = threadIdx.x;
    const float* xb = xyz + (size_t)b * 3 * NN;

    for (int i = tid; i < NN; i += 1024) {
        sx[i] = xb[i];
        sy[i] = xb[NN + i];
        sz[i] = xb[2 * NN + i];
        dist[i] = 1e10f;
    }
    if (tid == 0) scur[0] = 0;
    __syncthreads();

    const int lane = tid & 31, wid = tid >> 5;

    for (int it = 0; it < NP; ++it) {
        const int cur = scur[0];
        const float c0 = sx[cur], c1 = sy[cur], c2 = sz[cur];
        if (tid == 0) {
            g_newxyz[((size_t)b * NP + it) * 3 + 0] = c0;
            g_newxyz[((size_t)b * NP + it) * 3 + 1] = c1;
            g_newxyz[((size_t)b * NP + it) * 3 + 2] = c2;
            out1[(size_t)b * 3 * NP + it]            = c0;
            out1[(size_t)b * 3 * NP + NP + it]       = c1;
            out1[(size_t)b * 3 * NP + 2 * NP + it]   = c2;
        }
        float best = -1.0f;
        int   bidx = 0;
        for (int i = tid; i < NN; i += 1024) {
            // match XLA elementwise: squares computed separately, summed (no FMA contraction)
            float dx = __fsub_rn(sx[i], c0);
            float dy = __fsub_rn(sy[i], c1);
            float dz = __fsub_rn(sz[i], c2);
            float d  = __fadd_rn(__fadd_rn(__fmul_rn(dx, dx), __fmul_rn(dy, dy)),
                                 __fmul_rn(dz, dz));
            float nd = fminf(dist[i], d);
            dist[i]  = nd;
            if (nd > best) { best = nd; bidx = i; }   // first-occurrence within thread
        }
#pragma unroll
        for (int off = 16; off; off >>= 1) {
            float ov = __shfl_down_sync(0xffffffffu, best, off);
            int   oi = __shfl_down_sync(0xffffffffu, bidx, off);
            if (ov > best || (ov == best && oi < bidx)) { best = ov; bidx = oi; }
        }
        if (lane == 0) { wval[wid] = best; widx[wid] = bidx; }
        __syncthreads();
        if (wid == 0) {
            best = wval[lane];
            bidx = widx[lane];
#pragma unroll
            for (int off = 16; off; off >>= 1) {
                float ov = __shfl_down_sync(0xffffffffu, best, off);
                int   oi = __shfl_down_sync(0xffffffffu, bidx, off);
                if (ov > best || (ov == best && oi < bidx)) { best = ov; bidx = oi; }
            }
            if (lane == 0) scur[0] = bidx;
        }
        __syncthreads();
    }
}

// ---------------- ball query: warp per center, xyz in smem ----------------
__global__ void __launch_bounds__(256) ballquery_kernel(const float* __restrict__ xyz) {
    extern __shared__ float sm[];
    float* sx = sm;
    float* sy = sm + NN;
    float* sz = sm + 2 * NN;

    const int b   = blockIdx.y;
    const int tid = threadIdx.x;
    const float* xb = xyz + (size_t)b * 3 * NN;
    for (int i = tid; i < NN; i += 256) {
        sx[i] = xb[i]; sy[i] = xb[NN + i]; sz[i] = xb[2 * NN + i];
    }
    __syncthreads();

    const int wid = tid >> 5, lane = tid & 31;
    const int s = blockIdx.x * 8 + wid;
    const float r2 = (float)(0.2 * 0.2);   // float32(0.04)

    const float c0 = g_newxyz[((size_t)b * NP + s) * 3 + 0];
    const float c1 = g_newxyz[((size_t)b * NP + s) * 3 + 1];
    const float c2 = g_newxyz[((size_t)b * NP + s) * 3 + 2];
    // |c|^2 from elementwise fusion: separate rounds (proven by exact FPS output)
    const float sqc = __fadd_rn(__fadd_rn(__fmul_rn(c0, c0), __fmul_rn(c1, c1)),
                                __fmul_rn(c2, c2));
    const size_t gbase = ((size_t)b * NP + s) * NS;

    int count = 0;
    int firstIdx = -1;
    for (int base = 0; base < NN && count < NS; base += 32) {
        const int i = base + lane;
        const float x = sx[i], y = sy[i], z = sz[i];
        const float sqx = __fadd_rn(__fadd_rn(__fmul_rn(x, x), __fmul_rn(y, y)),
                                    __fmul_rn(z, z));
        // cross term is a dot_general (K=3 GEMM) in the reference -> FMA chain from 0
        const float cx = fmaf(c2, z, fmaf(c1, y, __fmul_rn(c0, x)));
        const float sqr = __fsub_rn(__fadd_rn(sqc, sqx), __fmul_rn(2.0f, cx));
        const bool hit = !(sqr > r2);
        const unsigned mask = __ballot_sync(0xffffffffu, hit);
        if (firstIdx < 0 && mask) firstIdx = base + __ffs(mask) - 1;
        if (hit) {
            int slot = count + __popc(mask & ((1u << lane) - 1u));
            if (slot < NS) g_gi[gbase + slot] = i;
        }
        count += __popc(mask);
    }
    int cnt = count < NS ? count : NS;
    for (int j = cnt + lane; j < NS; j += 32) g_gi[gbase + j] = firstIdx;
}

// ---------------- grouped attention + max pool (block per group) ----------------
// smem layout (floats):
//  ft 0..2047 | qm 2048..4095 | km 4096..6175 (stride65) | vm 6176..8255 (stride65)
//  om 8256..10303 | Wq 10304 | Wk 14400 | Wv 18496 | Wo 22592 | Wp 26688 | Bp 26880
//  px 26944 | py 26976 | pz 27008 | aw 27040 (8x32) | red 27296 (4x64) | idx 27552 (32 int)
#define A1_SMEM_FLOATS 27584

__global__ void __launch_bounds__(256) attn1_kernel(
    const float* __restrict__ xyz, const float* __restrict__ points,
    const float* __restrict__ wq, const float* __restrict__ wk,
    const float* __restrict__ wv, const float* __restrict__ wo,
    const float* __restrict__ wp, const float* __restrict__ bp) {
    extern __shared__ float sm[];
    float* ft = sm;
    float* qm = sm + 2048;
    float* km = sm + 4096;
    float* vm = sm + 6176;
    float* om = sm + 8256;
    float* Wq = sm + 10304;
    float* Wk = sm + 14400;
    float* Wv = sm + 18496;
    float* Wo = sm + 22592;
    float* Wp = sm + 26688;
    float* Bp = sm + 26880;
    float* px = sm + 26944;
    float* py = sm + 26976;
    float* pz = sm + 27008;
    float* aw = sm + 27040;
    float* red = sm + 27296;
    int* sidx = (int*)(sm + 27552);

    const int g   = blockIdx.x;          // g = b*NP + s
    const int b   = g >> 11;
    const int tid = threadIdx.x;

    for (int i = tid; i < 4096; i += 256) {
        Wq[i] = wq[i]; Wk[i] = wk[i]; Wv[i] = wv[i]; Wo[i] = wo[i];
    }
    if (tid < 192) Wp[tid] = wp[tid];
    if (tid < 64)  Bp[tid] = bp[tid];
    if (tid < 32) {
        const int id = g_gi[(size_t)g * NS + tid];
        sidx[tid] = id;
        const float c0 = g_newxyz[(size_t)g * 3 + 0];
        const float c1 = g_newxyz[(size_t)g * 3 + 1];
        const float c2 = g_newxyz[(size_t)g * 3 + 2];
        const float X = xyz[(size_t)b * 3 * NN + id];
        const float Y = xyz[(size_t)b * 3 * NN + NN + id];
        const float Z = xyz[(size_t)b * 3 * NN + 2 * NN + id];
        px[tid] = X; py[tid] = Y; pz[tid] = Z;
        ft[tid * 64 + 0] = X - c0;
        ft[tid * 64 + 1] = Y - c1;
        ft[tid * 64 + 2] = Z - c2;
    }
    __syncthreads();

    // gather point features: ft[j][3+c] = points[b, c, idx_j]
    for (int i = tid; i < NS * DINC; i += 256) {
        const int c = i >> 5, j = i & 31;
        ft[j * 64 + 3 + c] = points[(size_t)b * DINC * NN + (size_t)c * NN + sidx[j]];
    }
    __syncthreads();

    // q/k/v projections
    for (int i = tid; i < 2048; i += 256) {
        const int t = i >> 6, d = i & 63;
        float aq = 0.f, ak = 0.f, av = 0.f;
        const float* frow = ft + t * 64;
#pragma unroll 8
        for (int e = 0; e < 64; ++e) {
            const float f = frow[e];
            aq += f * Wq[e * 64 + d];
            ak += f * Wk[e * 64 + d];
            av += f * Wv[e * 64 + d];
        }
        av += px[t] * Wp[d] + py[t] * Wp[64 + d] + pz[t] * Wp[128 + d] + Bp[d];
        qm[t * 64 + d] = aq;
        km[t * 65 + d] = ak;
        vm[t * 65 + d] = av;
    }
    __syncthreads();

    // attention: warp per query row (4 rows per warp)
    const int wid = tid >> 5, lane = tid & 31;
    for (int rep = 0; rep < 4; ++rep) {
        const int t = wid + rep * 8;
        const float* qrow = qm + t * 64;
        const float* krow = km + lane * 65;
        float sc = 0.f;
#pragma unroll 8
        for (int d = 0; d < 64; ++d) sc += qrow[d] * krow[d];
        sc *= 0.125f;
        float mx = sc;
#pragma unroll
        for (int off = 16; off; off >>= 1)
            mx = fmaxf(mx, __shfl_xor_sync(0xffffffffu, mx, off));
        const float p = expf(sc - mx);
        float ssum = p;
#pragma unroll
        for (int off = 16; off; off >>= 1)
            ssum += __shfl_xor_sync(0xffffffffu, ssum, off);
        aw[wid * 32 + lane] = p / ssum;
        __syncwarp();
        float a0 = 0.f, a1 = 0.f;
#pragma unroll 8
        for (int j = 0; j < 32; ++j) {
            const float a = aw[wid * 32 + j];
            a0 += a * vm[j * 65 + lane];
            a1 += a * vm[j * 65 + 32 + lane];
        }
        om[t * 64 + lane]      = a0;
        om[t * 64 + 32 + lane] = a1;
        __syncwarp();
    }
    __syncthreads();

    // z = ft + om @ Wo, then max over the 32 samples
    const int d = tid & 63, tg = tid >> 6;
    float m = -3.4e38f;
    for (int t = tg; t < 32; t += 4) {
        float acc = ft[t * 64 + d];
        const float* orow = om + t * 64;
#pragma unroll 8
        for (int e = 0; e < 64; ++e) acc += orow[e] * Wo[e * 64 + d];
        m = fmaxf(m, acc);
    }
    red[tg * 64 + d] = m;
    __syncthreads();
    if (tid < 64) {
        float mm = fmaxf(fmaxf(red[tid], red[64 + tid]),
                         fmaxf(red[128 + tid], red[192 + tid]));
        g_feat2[(size_t)g * 64 + tid] = mm;
    }
}

// ---------------- attn2 q/k/v projection (64-token tiles) ----------------
#define P2_SMEM_FLOATS 16832
__global__ void __launch_bounds__(256) proj2_kernel(
    const float* __restrict__ wq, const float* __restrict__ wk,
    const float* __restrict__ wv, const float* __restrict__ wp,
    const float* __restrict__ bp) {
    extern __shared__ float sm[];
    float* ft = sm;              // 4096
    float* Wq = sm + 4096;
    float* Wk = sm + 8192;
    float* Wv = sm + 12288;
    float* Wp = sm + 16384;      // 192
    float* Bp = sm + 16576;      // 64
    float* px = sm + 16640;
    float* py = sm + 16704;
    float* pz = sm + 16768;

    const int b  = blockIdx.x >> 5;
    const int t0 = (blockIdx.x & 31) << 6;
    const int tid = threadIdx.x;

    for (int i = tid; i < 4096; i += 256) {
        ft[i] = g_feat2[((size_t)b * NP + t0) * 64 + i];
        Wq[i] = wq[i]; Wk[i] = wk[i]; Wv[i] = wv[i];
    }
    if (tid < 192) Wp[tid] = wp[tid];
    if (tid < 64) {
        Bp[tid] = bp[tid];
        px[tid] = g_newxyz[((size_t)b * NP + t0 + tid) * 3 + 0];
        py[tid] = g_newxyz[((size_t)b * NP + t0 + tid) * 3 + 1];
        pz[tid] = g_newxyz[((size_t)b * NP + t0 + tid) * 3 + 2];
    }
    __syncthreads();

    for (int i = tid; i < 4096; i += 256) {
        const int t = i >> 6, d = i & 63;
        float aq = 0.f, ak = 0.f, av = 0.f;
        const float* frow = ft + t * 64;
#pragma unroll 8
        for (int e = 0; e < 64; ++e) {
            const float f = frow[e];
            aq += f * Wq[e * 64 + d];
            ak += f * Wk[e * 64 + d];
            av += f * Wv[e * 64 + d];
        }
        av += px[t] * Wp[d] + py[t] * Wp[64 + d] + pz[t] * Wp[128 + d] + Bp[d];
        const size_t o = ((size_t)b * NP + t0 + t) * 64 + d;
        g_q[o] = aq; g_k[o] = ak; g_v[o] = av;
    }
}

// ---------------- attn2: flash-style, warp per query ----------------
__global__ void __launch_bounds__(128) flash_kernel() {
    __shared__ float ks[4096];
    __shared__ float vsm[4096];
    const int b = blockIdx.y;
    const int wid = threadIdx.x >> 5, lane = threadIdx.x & 31;
    const int qi = blockIdx.x * 4 + wid;
    const size_t qoff = ((size_t)b * NP + qi) * 64;
    const float q0 = g_q[qoff + lane];
    const float q1 = g_q[qoff + 32 + lane];
    float m = -3.4e38f, l = 0.f, o0 = 0.f, o1 = 0.f;

    for (int chunk = 0; chunk < NP / 64; ++chunk) {
        __syncthreads();
        const size_t kb = ((size_t)b * NP + chunk * 64) * 64;
        for (int i = threadIdx.x; i < 4096; i += 128) {
            ks[i]  = g_k[kb + i];
            vsm[i] = g_v[kb + i];
        }
        __syncthreads();
#pragma unroll 4
        for (int j = 0; j < 64; ++j) {
            float s = q0 * ks[j * 64 + lane] + q1 * ks[j * 64 + 32 + lane];
#pragma unroll
            for (int off = 16; off; off >>= 1)
                s += __shfl_xor_sync(0xffffffffu, s, off);
            s *= 0.125f;
            if (s <= m) {
                const float p = expf(s - m);
                l  += p;
                o0 += p * vsm[j * 64 + lane];
                o1 += p * vsm[j * 64 + 32 + lane];
            } else {
                const float corr = expf(m - s);
                l  = l * corr + 1.f;
                o0 = o0 * corr + vsm[j * 64 + lane];
                o1 = o1 * corr + vsm[j * 64 + 32 + lane];
                m  = s;
            }
        }
    }
    g_o[qoff + lane]      = o0 / l;
    g_o[qoff + 32 + lane] = o1 / l;
}

// ---------------- final: z = feat2 + o @ Wo, write transposed ----------------
#define FIN_SMEM_FLOATS 12352
__global__ void __launch_bounds__(256) final_kernel(const float* __restrict__ wo,
                                                    float* __restrict__ out2) {
    extern __shared__ float sm[];
    float* ot = sm;          // 4096
    float* Wo = sm + 4096;   // 4096
    float* z  = sm + 8192;   // 64*65

    const int b  = blockIdx.x >> 5;
    const int t0 = (blockIdx.x & 31) << 6;
    const int tid = threadIdx.x;

    for (int i = tid; i < 4096; i += 256) {
        ot[i] = g_o[((size_t)b * NP + t0) * 64 + i];
        Wo[i] = wo[i];
    }
    __syncthreads();
    for (int i = tid; i < 4096; i += 256) {
        const int t = i >> 6, d = i & 63;
        float acc = g_feat2[((size_t)b * NP + t0 + t) * 64 + d];
        const float* orow = ot + t * 64;
#pragma unroll 8
        for (int e = 0; e < 64; ++e) acc += orow[e] * Wo[e * 64 + d];
        z[t * 65 + d] = acc;
    }
    __syncthreads();
    for (int i = tid; i < 4096; i += 256) {
        const int d = i >> 6, tt = i & 63;
        out2[(size_t)b * DD * NP + (size_t)d * NP + t0 + tt] = z[tt * 65 + d];
    }
}

// ---------------- launch ----------------
extern "C" void kernel_launch(void* const* d_in, const int* in_sizes, int n_in,
                              void* d_out, int out_size) {
    const float* xyz    = (const float*)d_in[0];
    const float* points = (const float*)d_in[1];
    const float* w1q = (const float*)d_in[2];
    const float* w1k = (const float*)d_in[3];
    const float* w1v = (const float*)d_in[4];
    const float* w1o = (const float*)d_in[5];
    const float* w1p = (const float*)d_in[6];
    const float* b1p = (const float*)d_in[7];
    const float* w2q = (const float*)d_in[8];
    const float* w2k = (const float*)d_in[9];
    const float* w2v = (const float*)d_in[10];
    const float* w2o = (const float*)d_in[11];
    const float* w2p = (const float*)d_in[12];
    const float* b2p = (const float*)d_in[13];

    float* out  = (float*)d_out;
    float* out2 = out + (size_t)BB * 3 * NP;

    const int smFps = (4 * NN + 32) * 4 + 32 * 4 + 16;
    const int smBq  = 3 * NN * 4;
    const int smA1  = A1_SMEM_FLOATS * 4;
    const int smP2  = P2_SMEM_FLOATS * 4;
    const int smFin = FIN_SMEM_FLOATS * 4;

    cudaFuncSetAttribute(fps_kernel,       cudaFuncAttributeMaxDynamicSharedMemorySize, smFps);
    cudaFuncSetAttribute(ballquery_kernel, cudaFuncAttributeMaxDynamicSharedMemorySize, smBq);
    cudaFuncSetAttribute(attn1_kernel,     cudaFuncAttributeMaxDynamicSharedMemorySize, smA1);
    cudaFuncSetAttribute(proj2_kernel,     cudaFuncAttributeMaxDynamicSharedMemorySize, smP2);
    cudaFuncSetAttribute(final_kernel,     cudaFuncAttributeMaxDynamicSharedMemorySize, smFin);

    fps_kernel<<<BB, 1024, smFps>>>(xyz, out);
    ballquery_kernel<<<dim3(NP / 8, BB), 256, smBq>>>(xyz);
    attn1_kernel<<<BB * NP, 256, smA1>>>(xyz, points, w1q, w1k, w1v, w1o, w1p, b1p);
    proj2_kernel<<<BB * (NP / 64), 256, smP2>>>(w2q, w2k, w2v, w2p, b2p);
    flash_kernel<<<dim3(NP / 4, BB), 128>>>();
    final_kernel<<<BB * (NP / 64), 256, smFin>>>(w2o, out2);
}